// round 11
// baseline (speedup 1.0000x reference)
#include <cuda_runtime.h>
#include <math.h>

#define BN   4
#define NP   4096
#define CC   128
#define KN1  16
#define TD   64
#define CIN  262
#define KZ   131          // 3 + C
#define MR   384          // 6 * 64 rows: Pq Pk Pv Sq Sk Sv
#define FULLM 0xffffffffu

// ---------------- scratch (static device memory; no allocs) ----------------
__device__ float d_Ut[KZ * MR];               // [k][r]
__device__ float d_Ub[MR];
__device__ float d_PS[(size_t)BN * NP * MR];  // [b][n][384] point-major
__device__ int   d_knn[BN * NP * KN1];
__device__ float d_res[(size_t)BN * NP * TD]; // [p][64]

// ---------------- kernel 0: prep ----------------
__global__ void prep_kernel(const float* __restrict__ wq, const float* __restrict__ bq,
                            const float* __restrict__ wk, const float* __restrict__ bk,
                            const float* __restrict__ wv, const float* __restrict__ bv) {
    int stride = gridDim.x * blockDim.x;
    int tid0 = blockIdx.x * blockDim.x + threadIdx.x;
    for (int i = tid0; i < KZ * MR; i += stride) {
        int c = i / MR, r = i % MR;
        int g = r >> 6, o = r & 63;
        int gs = g % 3;
        const float* w = (gs == 0) ? wq : (gs == 1) ? wk : wv;
        float val;
        if (g < 3) {
            val = (c < 3) ? w[o * CIN + c] : w[o * CIN + 6 + (c - 3)];
        } else {
            val = (c < 3) ? (w[o * CIN + 3 + c] - w[o * CIN + c])
                          : (w[o * CIN + 134 + (c - 3)] - w[o * CIN + 6 + (c - 3)]);
        }
        d_Ut[i] = val;
    }
    for (int i = tid0; i < MR; i += stride) {
        int g = i >> 6, o = i & 63;
        d_Ub[i] = (g == 3) ? bq[o] : (g == 4) ? bk[o] : (g == 5) ? bv[o] : 0.0f;
    }
}

// ---------------- kernel 1: PS GEMM  [384 x 131] @ [131 x 4096] per batch ----------------
// 128x64 tile, 256 threads, 8x4 micro-tile, smem-transpose epilogue for coalesced stores
#define GK1 44
#define APAD 132
#define ZPAD 68
#define TP   132                         // Ts pitch
#define SMF  (GK1 * APAD + GK1 * ZPAD)   // 8800 floats; Ts needs 64*132=8448 -> fits
__global__ __launch_bounds__(256) void gemm_kernel(const float* __restrict__ xyz,
                                                   const float* __restrict__ feature) {
    __shared__ __align__(16) float smem_buf[SMF];
    float* As = smem_buf;                // [k][m] 128 rows (+pad)
    float* Zs = smem_buf + GK1 * APAD;   // [k][n] 64 points (+pad)
    float* Ts = smem_buf;                // [n][m] transpose buffer (overlays As/Zs)

    int b  = blockIdx.z;
    int mb = blockIdx.y * 128;
    int nb = blockIdx.x * 64;
    int tid = threadIdx.x;
    int tx = tid & 15, ty = tid >> 4;

    float acc[8][4] = {};
    for (int kb = 0; kb < KZ; kb += GK1) {
        int kc = min(GK1, KZ - kb);
        __syncthreads();
        for (int i = tid; i < kc * 32; i += 256) {
            int k = i >> 5, m4 = i & 31;
            *(float4*)(As + k * APAD + m4 * 4) =
                *(const float4*)(d_Ut + (size_t)(kb + k) * MR + mb + m4 * 4);
        }
        for (int i = tid; i < kc * 64; i += 256) {
            int k = i >> 6, m = i & 63;
            int row = kb + k;
            const float* src = (row < 3) ? (xyz + ((size_t)b * 3 + row) * NP)
                                         : (feature + ((size_t)b * CC + (row - 3)) * NP);
            Zs[k * ZPAD + m] = src[nb + m];
        }
        __syncthreads();
        #pragma unroll 4
        for (int k = 0; k < kc; ++k) {
            float4 a0 = *(const float4*)(As + k * APAD + ty * 8);
            float4 a1 = *(const float4*)(As + k * APAD + ty * 8 + 4);
            float4 z4 = *(const float4*)(Zs + k * ZPAD + tx * 4);
            float ar[8] = {a0.x, a0.y, a0.z, a0.w, a1.x, a1.y, a1.z, a1.w};
            float zr[4] = {z4.x, z4.y, z4.z, z4.w};
            #pragma unroll
            for (int r = 0; r < 8; r++)
                #pragma unroll
                for (int j = 0; j < 4; j++)
                    acc[r][j] = fmaf(ar[r], zr[j], acc[r][j]);
        }
    }
    float4 ub0 = *(const float4*)(d_Ub + mb + ty * 8);
    float4 ub1 = *(const float4*)(d_Ub + mb + ty * 8 + 4);
    float ub[8] = {ub0.x, ub0.y, ub0.z, ub0.w, ub1.x, ub1.y, ub1.z, ub1.w};

    // transpose epilogue: regs -> Ts[n][m], then coalesced row stores
    __syncthreads();                      // done with As/Zs
    #pragma unroll
    for (int j = 0; j < 4; j++) {
        int n = tx * 4 + j;
        float4 t0, t1;
        t0.x = acc[0][j] + ub[0]; t0.y = acc[1][j] + ub[1];
        t0.z = acc[2][j] + ub[2]; t0.w = acc[3][j] + ub[3];
        t1.x = acc[4][j] + ub[4]; t1.y = acc[5][j] + ub[5];
        t1.z = acc[6][j] + ub[6]; t1.w = acc[7][j] + ub[7];
        *(float4*)(Ts + n * TP + ty * 8)     = t0;
        *(float4*)(Ts + n * TP + ty * 8 + 4) = t1;
    }
    __syncthreads();
    for (int i = tid; i < 64 * 32; i += 256) {
        int n = i >> 5, c = i & 31;       // warp = one point's 512B row segment
        *(float4*)(d_PS + ((size_t)b * NP + nb + n) * MR + mb + c * 4) =
            *(const float4*)(Ts + n * TP + c * 4);
    }
}

// ---------------- kernel 2: KNN — warp top-17, 4-candidate batched ballot ----------------
#define KTC 1024
__global__ __launch_bounds__(256) void knn_kernel(const float* __restrict__ xyz) {
    __shared__ float4 cand[KTC];
    int b    = blockIdx.y;
    int tid  = threadIdx.x;
    int warp = tid >> 5;
    int lane = tid & 31;
    int n    = blockIdx.x * 8 + warp;

    const float* xb = xyz + (size_t)b * 3 * NP;
    float qx = __ldg(xb + n), qy = __ldg(xb + NP + n), qz = __ldg(xb + 2 * NP + n);

    const float INFF = __int_as_float(0x7f800000);
    float v = INFF;        // lane l (l<17) holds rank-l key (ascending)
    int   vi = 0x7fffffff;
    float tau = INFF;      // rank-16 key, warp-uniform

    for (int t = 0; t < NP / KTC; t++) {
        int base = t * KTC;
        for (int i = tid; i < KTC; i += 256) {
            int c = base + i;
            float x = __ldg(xb + c), y = __ldg(xb + NP + c), z = __ldg(xb + 2 * NP + c);
            float sq = fmaf(x, x, fmaf(y, y, z * z));
            cand[i] = make_float4(x, y, z, sq);
        }
        __syncthreads();
        for (int s = 0; s < KTC / 128; s++) {
            float4 c0 = cand[s * 128 + lane];
            float4 c1 = cand[s * 128 + 32 + lane];
            float4 c2 = cand[s * 128 + 64 + lane];
            float4 c3 = cand[s * 128 + 96 + lane];
            float k0 = fmaf(-2.0f, fmaf(c0.x, qx, fmaf(c0.y, qy, c0.z * qz)), c0.w);
            float k1 = fmaf(-2.0f, fmaf(c1.x, qx, fmaf(c1.y, qy, c1.z * qz)), c1.w);
            float k2 = fmaf(-2.0f, fmaf(c2.x, qx, fmaf(c2.y, qy, c2.z * qz)), c2.w);
            float k3 = fmaf(-2.0f, fmaf(c3.x, qx, fmaf(c3.y, qy, c3.z * qz)), c3.w);
            float kmin = fminf(fminf(k0, k1), fminf(k2, k3));
            unsigned mask = __ballot_sync(FULLM, kmin < tau);
            while (mask) {                           // bounded: popcount(mask) iters max
                int src = __ffs(mask) - 1;
                mask &= mask - 1;
                float e0 = __shfl_sync(FULLM, k0, src);
                float e1 = __shfl_sync(FULLM, k1, src);
                float e2 = __shfl_sync(FULLM, k2, src);
                float e3 = __shfl_sync(FULLM, k3, src);
                int ib = base + s * 128 + src;
                #pragma unroll
                for (int j = 0; j < 4; j++) {
                    float kk = (j == 0) ? e0 : (j == 1) ? e1 : (j == 2) ? e2 : e3;
                    if (kk < tau) {                  // warp-uniform predicate
                        int kc = ib + 32 * j;
                        unsigned pm = __ballot_sync(FULLM, (lane < 17) && (kk < v));
                        int pos = __ffs(pm) - 1;
                        float vp = __shfl_up_sync(FULLM, v, 1);
                        int   ip = __shfl_up_sync(FULLM, vi, 1);
                        if (lane < 17 && lane >= pos) {
                            if (lane == pos) { v = kk; vi = kc; }
                            else             { v = vp; vi = ip; }
                        }
                        tau = __shfl_sync(FULLM, v, 16);
                    }
                }
            }
        }
        __syncthreads();
    }
    if (lane >= 1 && lane < 17)                      // rank 0 == self, dropped
        d_knn[((size_t)b * NP + n) * KN1 + (lane - 1)] = vi;
}

// ---------------- kernel 3: attention -> res (1 block / point; warp0 2x2 dot tiling) ----------------
__global__ __launch_bounds__(128) void attn_kernel(float* __restrict__ resout) {
    __shared__ float4 qsm[8][17], ksm[16][17], vsm[16][17];
    __shared__ float  S_[192];       // Sq, Sk, Sv
    __shared__ int    idxsm[16];
    __shared__ float  ssm[16];

    int p   = blockIdx.x;           // p = b*NP + f
    int tid = threadIdx.x;
    const float* psb = d_PS + (size_t)p * MR;

    if (tid < 48) ((float4*)S_)[tid] = ((const float4*)(psb + 192))[tid];
    if (tid < 16) idxsm[tid] = d_knn[(size_t)p * KN1 + tid];
    __syncthreads();

    int bbase = (p >> 12) * NP;
    for (int i = tid; i < 640; i += 128) {
        int row = i >> 4, c4 = i & 15;
        if (row < 16) {
            const float4* src = (const float4*)(d_PS + ((size_t)(bbase + idxsm[row])) * MR + 64);
            float4 a = src[c4], s = ((const float4*)(S_ + 64))[c4];
            ksm[row][c4] = make_float4(a.x + s.x, a.y + s.y, a.z + s.z, a.w + s.w);
        } else if (row < 32) {
            int j = row - 16;
            const float4* src = (const float4*)(d_PS + ((size_t)(bbase + idxsm[j])) * MR + 128);
            vsm[j][c4] = src[c4];
        } else {
            int nn = row - 32;
            const float4* src = (const float4*)(d_PS + ((size_t)(bbase + idxsm[nn])) * MR);
            float4 a = src[c4], s = ((const float4*)S_)[c4];
            qsm[nn][c4] = make_float4(a.x + s.x, a.y + s.y, a.z + s.z, a.w + s.w);
        }
    }
    __syncthreads();

    // warp 0: each thread owns attn[2pn..2pn+1][2pj..2pj+1]
    if (tid < 32) {
        int pn = tid >> 3, pj = tid & 7;
        float a00 = 0.f, a01 = 0.f, a10 = 0.f, a11 = 0.f;
        #pragma unroll
        for (int c4 = 0; c4 < 16; c4++) {
            float4 qa = qsm[2 * pn][c4],     qb = qsm[2 * pn + 1][c4];
            float4 ka = ksm[2 * pj][c4],     kb = ksm[2 * pj + 1][c4];
            a00 = fmaf(qa.x, ka.x, a00); a00 = fmaf(qa.y, ka.y, a00);
            a00 = fmaf(qa.z, ka.z, a00); a00 = fmaf(qa.w, ka.w, a00);
            a01 = fmaf(qa.x, kb.x, a01); a01 = fmaf(qa.y, kb.y, a01);
            a01 = fmaf(qa.z, kb.z, a01); a01 = fmaf(qa.w, kb.w, a01);
            a10 = fmaf(qb.x, ka.x, a10); a10 = fmaf(qb.y, ka.y, a10);
            a10 = fmaf(qb.z, ka.z, a10); a10 = fmaf(qb.w, ka.w, a10);
            a11 = fmaf(qb.x, kb.x, a11); a11 = fmaf(qb.y, kb.y, a11);
            a11 = fmaf(qb.z, kb.z, a11); a11 = fmaf(qb.w, kb.w, a11);
        }
        // softmax over j (16 entries per nq row): reduce across pj lanes (bits 1,2,4)
        float m0 = fmaxf(a00, a01), m1 = fmaxf(a10, a11);
        #pragma unroll
        for (int off = 1; off < 8; off <<= 1) {
            m0 = fmaxf(m0, __shfl_xor_sync(FULLM, m0, off));
            m1 = fmaxf(m1, __shfl_xor_sync(FULLM, m1, off));
        }
        float e00 = __expf(a00 - m0), e01 = __expf(a01 - m0);
        float e10 = __expf(a10 - m1), e11 = __expf(a11 - m1);
        float s0 = e00 + e01, s1 = e10 + e11;
        #pragma unroll
        for (int off = 1; off < 8; off <<= 1) {
            s0 += __shfl_xor_sync(FULLM, s0, off);
            s1 += __shfl_xor_sync(FULLM, s1, off);
        }
        float inv0 = 1.0f / s0, inv1 = 1.0f / s1;
        // s_j = sum over 8 nq of p[nq][j]: local (nq pair) + reduce across pn lanes (bits 8,16)
        float sj0 = e00 * inv0 + e10 * inv1;   // column j = 2pj
        float sj1 = e01 * inv0 + e11 * inv1;   // column j = 2pj+1
        #pragma unroll
        for (int off = 8; off < 32; off <<= 1) {
            sj0 += __shfl_xor_sync(FULLM, sj0, off);
            sj1 += __shfl_xor_sync(FULLM, sj1, off);
        }
        if (tid < 8) { ssm[2 * tid] = sj0; ssm[2 * tid + 1] = sj1; }
    }
    __syncthreads();

    if (tid < 64) {
        const float* vf = (const float*)vsm;
        float r_ = 8.0f * S_[128 + tid];           // sum_j s_j == 8
        #pragma unroll
        for (int jj = 0; jj < 16; jj++) r_ = fmaf(ssm[jj], vf[jj * 68 + tid], r_);
        resout[(size_t)p * TD + tid] = r_;
    }
}

// ---------------- kernel 4: out = w1 @ res^T + b1 + feature ----------------
#define G2S 68
__global__ __launch_bounds__(256) void gemm2_kernel(const float* __restrict__ w1,
                                                    const float* __restrict__ b1,
                                                    const float* __restrict__ feature,
                                                    float* __restrict__ out) {
    __shared__ float As[TD * G2S];   // [k][c]
    __shared__ float Bs[TD * G2S];   // [k][n]
    int tid = threadIdx.x;
    int cb  = blockIdx.y * 64;
    int gp  = blockIdx.x * 64;       // global point base (64 | 4096 -> single batch)
    int tx = tid & 15, ty = tid >> 4;

    for (int i = tid; i < 64 * 64; i += 256) {
        int c = i & 63, k = i >> 6;
        As[k * G2S + c] = w1[(cb + c) * TD + k];
    }
    for (int i = tid; i < 64 * 16; i += 256) {
        int n = i >> 4, m4 = i & 15;
        float4 r4 = *(const float4*)(d_res + ((size_t)(gp + n)) * TD + m4 * 4);
        Bs[(m4 * 4 + 0) * G2S + n] = r4.x;
        Bs[(m4 * 4 + 1) * G2S + n] = r4.y;
        Bs[(m4 * 4 + 2) * G2S + n] = r4.z;
        Bs[(m4 * 4 + 3) * G2S + n] = r4.w;
    }
    __syncthreads();

    float acc[4][4] = {};  // [c][n]
    #pragma unroll 8
    for (int k = 0; k < TD; k++) {
        float4 a4 = *(const float4*)(As + k * G2S + ty * 4);
        float4 b4 = *(const float4*)(Bs + k * G2S + tx * 4);
        float ar[4] = {a4.x, a4.y, a4.z, a4.w};
        float br[4] = {b4.x, b4.y, b4.z, b4.w};
        #pragma unroll
        for (int i2 = 0; i2 < 4; i2++)
            #pragma unroll
            for (int j2 = 0; j2 < 4; j2++)
                acc[i2][j2] = fmaf(ar[i2], br[j2], acc[i2][j2]);
    }

    int b = gp >> 12;
    int f0 = (gp & 4095) + tx * 4;
    #pragma unroll
    for (int i2 = 0; i2 < 4; i2++) {
        int c = cb + ty * 4 + i2;
        float bias = __ldg(b1 + c);
        size_t addr = ((size_t)(b * CC + c)) * NP + f0;
        float4 fea = *(const float4*)(feature + addr);
        float4 o4;
        o4.x = acc[i2][0] + bias + fea.x;
        o4.y = acc[i2][1] + bias + fea.y;
        o4.z = acc[i2][2] + bias + fea.z;
        o4.w = acc[i2][3] + bias + fea.w;
        *(float4*)(out + addr) = o4;
    }
}

// ---------------- launch ----------------
extern "C" void kernel_launch(void* const* d_in, const int* in_sizes, int n_in,
                              void* d_out, int out_size) {
    const float* feature = (const float*)d_in[0];
    const float* xyz     = (const float*)d_in[1];
    const float* wq      = (const float*)d_in[2];
    const float* bq      = (const float*)d_in[3];
    const float* wk      = (const float*)d_in[4];
    const float* bk      = (const float*)d_in[5];
    const float* wv      = (const float*)d_in[6];
    const float* bv      = (const float*)d_in[7];
    const float* w1      = (const float*)d_in[8];
    const float* b1      = (const float*)d_in[9];
    float* out = (float*)d_out;

    static cudaStream_t s2 = nullptr;
    static cudaEvent_t  evFork = nullptr, evJoin = nullptr;
    if (s2 == nullptr) {
        cudaStreamCreateWithFlags(&s2, cudaStreamNonBlocking);
        cudaEventCreateWithFlags(&evFork, cudaEventDisableTiming);
        cudaEventCreateWithFlags(&evJoin, cudaEventDisableTiming);
    }

    float* resbuf;
    cudaGetSymbolAddress((void**)&resbuf, d_res);

    // fork: knn runs on s2 concurrently with prep+gemm1 on the main stream
    cudaEventRecord(evFork, 0);
    cudaStreamWaitEvent(s2, evFork, 0);
    knn_kernel<<<dim3(512, 4), 256, 0, s2>>>(xyz);
    cudaEventRecord(evJoin, s2);

    prep_kernel<<<96, 256>>>(wq, bq, wk, bk, wv, bv);
    gemm_kernel<<<dim3(64, 3, 4), 256>>>(xyz, feature);

    // join before attention (needs both PS and knn)
    cudaStreamWaitEvent(0, evJoin, 0);
    attn_kernel<<<BN * NP, 128>>>(resbuf);
    gemm2_kernel<<<dim3(256, 2), 256>>>(w1, b1, feature, out);
}

// round 14
// speedup vs baseline: 1.0426x; 1.0426x over previous
#include <cuda_runtime.h>
#include <math.h>

#define BN   4
#define NP   4096
#define CC   128
#define KN1  16
#define TD   64
#define CIN  262
#define KZ   131          // 3 + C
#define MR   384          // 6 * 64 rows: Pq Pk Pv Sq Sk Sv
#define FULLM 0xffffffffu

// ---------------- scratch (static device memory; no allocs) ----------------
__device__ float d_Ut[KZ * MR];               // [k][r]
__device__ float d_Ub[MR];
__device__ float d_PS[(size_t)BN * NP * MR];  // [b][n][384] point-major
__device__ int   d_knn[BN * NP * KN1];
__device__ float d_res[(size_t)BN * NP * TD]; // [p][64]

// ---------------- cp.async helpers ----------------
__device__ __forceinline__ void cpa16(void* dst, const void* src) {
    unsigned d = (unsigned)__cvta_generic_to_shared(dst);
    asm volatile("cp.async.ca.shared.global [%0], [%1], 16;\n" :: "r"(d), "l"(src));
}
#define CP_COMMIT() asm volatile("cp.async.commit_group;\n" ::: "memory")
#define CP_WAIT1()  asm volatile("cp.async.wait_group 1;\n" ::: "memory")
#define CP_WAIT0()  asm volatile("cp.async.wait_group 0;\n" ::: "memory")

// ---------------- kernel 0: prep ----------------
__global__ void prep_kernel(const float* __restrict__ wq, const float* __restrict__ bq,
                            const float* __restrict__ wk, const float* __restrict__ bk,
                            const float* __restrict__ wv, const float* __restrict__ bv) {
    int stride = gridDim.x * blockDim.x;
    int tid0 = blockIdx.x * blockDim.x + threadIdx.x;
    for (int i = tid0; i < KZ * MR; i += stride) {
        int c = i / MR, r = i % MR;
        int g = r >> 6, o = r & 63;
        int gs = g % 3;
        const float* w = (gs == 0) ? wq : (gs == 1) ? wk : wv;
        float val;
        if (g < 3) {
            val = (c < 3) ? w[o * CIN + c] : w[o * CIN + 6 + (c - 3)];
        } else {
            val = (c < 3) ? (w[o * CIN + 3 + c] - w[o * CIN + c])
                          : (w[o * CIN + 134 + (c - 3)] - w[o * CIN + 6 + (c - 3)]);
        }
        d_Ut[i] = val;
    }
    for (int i = tid0; i < MR; i += stride) {
        int g = i >> 6, o = i & 63;
        d_Ub[i] = (g == 3) ? bq[o] : (g == 4) ? bk[o] : (g == 5) ? bv[o] : 0.0f;
    }
}

// ---------------- kernel 1: PS GEMM [384 x 131] @ [131 x 4096] per batch ----------------
// 128x64 tile, 256 threads, 8x4 micro-tile, cp.async double-buffered k-chunks
#define GKC 22
#define NCH 6            // 5*22 + 21 = 131
#define APAD 132
#define ZPAD 68
__global__ __launch_bounds__(256) void gemm_kernel(const float* __restrict__ xyz,
                                                   const float* __restrict__ feature) {
    __shared__ __align__(16) float As[2][GKC * APAD];   // [buf][k][m]
    __shared__ __align__(16) float Zs[2][GKC * ZPAD];   // [buf][k][n]
    int b  = blockIdx.z;
    int mb = blockIdx.y * 128;
    int nb = blockIdx.x * 64;
    int tid = threadIdx.x;
    int tx = tid & 15, ty = tid >> 4;

    // stage chunk c into buffer buf (cp.async, 16B granules)
    auto stage = [&](int c, int buf) {
        int kbase = c * GKC;
        int kc = min(GKC, KZ - kbase);
        for (int i = tid; i < kc * 32; i += 256) {          // As: kc rows x 32 float4
            int k = i >> 5, m4 = i & 31;
            cpa16(&As[buf][k * APAD + m4 * 4],
                  d_Ut + (size_t)(kbase + k) * MR + mb + m4 * 4);
        }
        for (int i = tid; i < kc * 16; i += 256) {          // Zs: kc rows x 16 float4
            int k = i >> 4, m4 = i & 15;
            int row = kbase + k;
            const float* src = (row < 3) ? (xyz + ((size_t)b * 3 + row) * NP)
                                         : (feature + ((size_t)b * CC + (row - 3)) * NP);
            cpa16(&Zs[buf][k * ZPAD + m4 * 4], src + nb + m4 * 4);
        }
    };

    float acc[8][4] = {};
    stage(0, 0); CP_COMMIT();
    for (int c = 0; c < NCH; c++) {
        if (c + 1 < NCH) { stage(c + 1, (c + 1) & 1); CP_COMMIT(); CP_WAIT1(); }
        else             { CP_WAIT0(); }
        __syncthreads();
        const float* Ab = As[c & 1];
        const float* Zb = Zs[c & 1];
        int kc = min(GKC, KZ - c * GKC);
        #pragma unroll 2
        for (int k = 0; k < kc; ++k) {
            float4 a0 = *(const float4*)(Ab + k * APAD + ty * 8);
            float4 a1 = *(const float4*)(Ab + k * APAD + ty * 8 + 4);
            float4 z4 = *(const float4*)(Zb + k * ZPAD + tx * 4);
            float ar[8] = {a0.x, a0.y, a0.z, a0.w, a1.x, a1.y, a1.z, a1.w};
            float zr[4] = {z4.x, z4.y, z4.z, z4.w};
            #pragma unroll
            for (int r = 0; r < 8; r++)
                #pragma unroll
                for (int j = 0; j < 4; j++)
                    acc[r][j] = fmaf(ar[r], zr[j], acc[r][j]);
        }
        __syncthreads();                                    // before buffer reuse
    }

    float4 ub0 = *(const float4*)(d_Ub + mb + ty * 8);
    float4 ub1 = *(const float4*)(d_Ub + mb + ty * 8 + 4);
    float ub[8] = {ub0.x, ub0.y, ub0.z, ub0.w, ub1.x, ub1.y, ub1.z, ub1.w};
    #pragma unroll
    for (int j = 0; j < 4; j++) {
        size_t n = (size_t)b * NP + nb + tx * 4 + j;
        float4 o0, o1;
        o0.x = acc[0][j] + ub[0]; o0.y = acc[1][j] + ub[1];
        o0.z = acc[2][j] + ub[2]; o0.w = acc[3][j] + ub[3];
        o1.x = acc[4][j] + ub[4]; o1.y = acc[5][j] + ub[5];
        o1.z = acc[6][j] + ub[6]; o1.w = acc[7][j] + ub[7];
        *(float4*)(d_PS + n * MR + mb + ty * 8)     = o0;
        *(float4*)(d_PS + n * MR + mb + ty * 8 + 4) = o1;
    }
}

// ---------------- kernel 2: KNN — warp top-17, 4-candidate batched ballot ----------------
#define KTC 1024
__global__ __launch_bounds__(256) void knn_kernel(const float* __restrict__ xyz) {
    __shared__ float4 cand[KTC];
    int b    = blockIdx.y;
    int tid  = threadIdx.x;
    int warp = tid >> 5;
    int lane = tid & 31;
    int n    = blockIdx.x * 8 + warp;

    const float* xb = xyz + (size_t)b * 3 * NP;
    float qx = __ldg(xb + n), qy = __ldg(xb + NP + n), qz = __ldg(xb + 2 * NP + n);

    const float INFF = __int_as_float(0x7f800000);
    float v = INFF;        // lane l (l<17) holds rank-l key (ascending)
    int   vi = 0x7fffffff;
    float tau = INFF;      // rank-16 key, warp-uniform

    for (int t = 0; t < NP / KTC; t++) {
        int base = t * KTC;
        for (int i = tid; i < KTC; i += 256) {
            int c = base + i;
            float x = __ldg(xb + c), y = __ldg(xb + NP + c), z = __ldg(xb + 2 * NP + c);
            float sq = fmaf(x, x, fmaf(y, y, z * z));
            cand[i] = make_float4(x, y, z, sq);
        }
        __syncthreads();
        for (int s = 0; s < KTC / 128; s++) {
            float4 c0 = cand[s * 128 + lane];
            float4 c1 = cand[s * 128 + 32 + lane];
            float4 c2 = cand[s * 128 + 64 + lane];
            float4 c3 = cand[s * 128 + 96 + lane];
            float k0 = fmaf(-2.0f, fmaf(c0.x, qx, fmaf(c0.y, qy, c0.z * qz)), c0.w);
            float k1 = fmaf(-2.0f, fmaf(c1.x, qx, fmaf(c1.y, qy, c1.z * qz)), c1.w);
            float k2 = fmaf(-2.0f, fmaf(c2.x, qx, fmaf(c2.y, qy, c2.z * qz)), c2.w);
            float k3 = fmaf(-2.0f, fmaf(c3.x, qx, fmaf(c3.y, qy, c3.z * qz)), c3.w);
            float kmin = fminf(fminf(k0, k1), fminf(k2, k3));
            unsigned mask = __ballot_sync(FULLM, kmin < tau);
            while (mask) {                           // bounded: popcount(mask) iters max
                int src = __ffs(mask) - 1;
                mask &= mask - 1;
                float e0 = __shfl_sync(FULLM, k0, src);
                float e1 = __shfl_sync(FULLM, k1, src);
                float e2 = __shfl_sync(FULLM, k2, src);
                float e3 = __shfl_sync(FULLM, k3, src);
                int ib = base + s * 128 + src;
                #pragma unroll
                for (int j = 0; j < 4; j++) {
                    float kk = (j == 0) ? e0 : (j == 1) ? e1 : (j == 2) ? e2 : e3;
                    if (kk < tau) {                  // warp-uniform predicate
                        int kc = ib + 32 * j;
                        unsigned pm = __ballot_sync(FULLM, (lane < 17) && (kk < v));
                        int pos = __ffs(pm) - 1;
                        float vp = __shfl_up_sync(FULLM, v, 1);
                        int   ip = __shfl_up_sync(FULLM, vi, 1);
                        if (lane < 17 && lane >= pos) {
                            if (lane == pos) { v = kk; vi = kc; }
                            else             { v = vp; vi = ip; }
                        }
                        tau = __shfl_sync(FULLM, v, 16);
                    }
                }
            }
        }
        __syncthreads();
    }
    if (lane >= 1 && lane < 17)                      // rank 0 == self, dropped
        d_knn[((size_t)b * NP + n) * KN1 + (lane - 1)] = vi;
}

// ---------------- kernel 3: attention -> res (1 block / point; warp0 2x2 dot tiling) ----------------
__global__ __launch_bounds__(128) void attn_kernel(float* __restrict__ resout) {
    __shared__ float4 qsm[8][17], ksm[16][17], vsm[16][17];
    __shared__ float  S_[192];       // Sq, Sk, Sv
    __shared__ int    idxsm[16];
    __shared__ float  ssm[16];

    int p   = blockIdx.x;           // p = b*NP + f
    int tid = threadIdx.x;
    const float* psb = d_PS + (size_t)p * MR;

    if (tid < 48) ((float4*)S_)[tid] = ((const float4*)(psb + 192))[tid];
    if (tid < 16) idxsm[tid] = d_knn[(size_t)p * KN1 + tid];
    __syncthreads();

    int bbase = (p >> 12) * NP;
    for (int i = tid; i < 640; i += 128) {
        int row = i >> 4, c4 = i & 15;
        if (row < 16) {
            const float4* src = (const float4*)(d_PS + ((size_t)(bbase + idxsm[row])) * MR + 64);
            float4 a = src[c4], s = ((const float4*)(S_ + 64))[c4];
            ksm[row][c4] = make_float4(a.x + s.x, a.y + s.y, a.z + s.z, a.w + s.w);
        } else if (row < 32) {
            int j = row - 16;
            const float4* src = (const float4*)(d_PS + ((size_t)(bbase + idxsm[j])) * MR + 128);
            vsm[j][c4] = src[c4];
        } else {
            int nn = row - 32;
            const float4* src = (const float4*)(d_PS + ((size_t)(bbase + idxsm[nn])) * MR);
            float4 a = src[c4], s = ((const float4*)S_)[c4];
            qsm[nn][c4] = make_float4(a.x + s.x, a.y + s.y, a.z + s.z, a.w + s.w);
        }
    }
    __syncthreads();

    // warp 0: each thread owns attn[2pn..2pn+1][2pj..2pj+1]
    if (tid < 32) {
        int pn = tid >> 3, pj = tid & 7;
        float a00 = 0.f, a01 = 0.f, a10 = 0.f, a11 = 0.f;
        #pragma unroll
        for (int c4 = 0; c4 < 16; c4++) {
            float4 qa = qsm[2 * pn][c4],     qb = qsm[2 * pn + 1][c4];
            float4 ka = ksm[2 * pj][c4],     kb = ksm[2 * pj + 1][c4];
            a00 = fmaf(qa.x, ka.x, a00); a00 = fmaf(qa.y, ka.y, a00);
            a00 = fmaf(qa.z, ka.z, a00); a00 = fmaf(qa.w, ka.w, a00);
            a01 = fmaf(qa.x, kb.x, a01); a01 = fmaf(qa.y, kb.y, a01);
            a01 = fmaf(qa.z, kb.z, a01); a01 = fmaf(qa.w, kb.w, a01);
            a10 = fmaf(qb.x, ka.x, a10); a10 = fmaf(qb.y, ka.y, a10);
            a10 = fmaf(qb.z, ka.z, a10); a10 = fmaf(qb.w, ka.w, a10);
            a11 = fmaf(qb.x, kb.x, a11); a11 = fmaf(qb.y, kb.y, a11);
            a11 = fmaf(qb.z, kb.z, a11); a11 = fmaf(qb.w, kb.w, a11);
        }
        float m0 = fmaxf(a00, a01), m1 = fmaxf(a10, a11);
        #pragma unroll
        for (int off = 1; off < 8; off <<= 1) {
            m0 = fmaxf(m0, __shfl_xor_sync(FULLM, m0, off));
            m1 = fmaxf(m1, __shfl_xor_sync(FULLM, m1, off));
        }
        float e00 = __expf(a00 - m0), e01 = __expf(a01 - m0);
        float e10 = __expf(a10 - m1), e11 = __expf(a11 - m1);
        float s0 = e00 + e01, s1 = e10 + e11;
        #pragma unroll
        for (int off = 1; off < 8; off <<= 1) {
            s0 += __shfl_xor_sync(FULLM, s0, off);
            s1 += __shfl_xor_sync(FULLM, s1, off);
        }
        float inv0 = 1.0f / s0, inv1 = 1.0f / s1;
        float sj0 = e00 * inv0 + e10 * inv1;   // column j = 2pj
        float sj1 = e01 * inv0 + e11 * inv1;   // column j = 2pj+1
        #pragma unroll
        for (int off = 8; off < 32; off <<= 1) {
            sj0 += __shfl_xor_sync(FULLM, sj0, off);
            sj1 += __shfl_xor_sync(FULLM, sj1, off);
        }
        if (tid < 8) { ssm[2 * tid] = sj0; ssm[2 * tid + 1] = sj1; }
    }
    __syncthreads();

    if (tid < 64) {
        const float* vf = (const float*)vsm;
        float r_ = 8.0f * S_[128 + tid];           // sum_j s_j == 8
        #pragma unroll
        for (int jj = 0; jj < 16; jj++) r_ = fmaf(ssm[jj], vf[jj * 68 + tid], r_);
        resout[(size_t)p * TD + tid] = r_;
    }
}

// ---------------- kernel 4: out = w1 @ res^T + b1 + feature ----------------
#define G2S 68
__global__ __launch_bounds__(256) void gemm2_kernel(const float* __restrict__ w1,
                                                    const float* __restrict__ b1,
                                                    const float* __restrict__ feature,
                                                    float* __restrict__ out) {
    __shared__ float As2[TD * G2S];   // [k][c]
    __shared__ float Bs2[TD * G2S];   // [k][n]
    int tid = threadIdx.x;
    int cb  = blockIdx.y * 64;
    int gp  = blockIdx.x * 64;       // global point base (64 | 4096 -> single batch)
    int tx = tid & 15, ty = tid >> 4;

    for (int i = tid; i < 64 * 64; i += 256) {
        int c = i & 63, k = i >> 6;
        As2[k * G2S + c] = w1[(cb + c) * TD + k];
    }
    for (int i = tid; i < 64 * 16; i += 256) {
        int n = i >> 4, m4 = i & 15;
        float4 r4 = *(const float4*)(d_res + ((size_t)(gp + n)) * TD + m4 * 4);
        Bs2[(m4 * 4 + 0) * G2S + n] = r4.x;
        Bs2[(m4 * 4 + 1) * G2S + n] = r4.y;
        Bs2[(m4 * 4 + 2) * G2S + n] = r4.z;
        Bs2[(m4 * 4 + 3) * G2S + n] = r4.w;
    }
    __syncthreads();

    float acc[4][4] = {};  // [c][n]
    #pragma unroll 8
    for (int k = 0; k < TD; k++) {
        float4 a4 = *(const float4*)(As2 + k * G2S + ty * 4);
        float4 b4 = *(const float4*)(Bs2 + k * G2S + tx * 4);
        float ar[4] = {a4.x, a4.y, a4.z, a4.w};
        float br[4] = {b4.x, b4.y, b4.z, b4.w};
        #pragma unroll
        for (int i2 = 0; i2 < 4; i2++)
            #pragma unroll
            for (int j2 = 0; j2 < 4; j2++)
                acc[i2][j2] = fmaf(ar[i2], br[j2], acc[i2][j2]);
    }

    int b = gp >> 12;
    int f0 = (gp & 4095) + tx * 4;
    #pragma unroll
    for (int i2 = 0; i2 < 4; i2++) {
        int c = cb + ty * 4 + i2;
        float bias = __ldg(b1 + c);
        size_t addr = ((size_t)(b * CC + c)) * NP + f0;
        float4 fea = *(const float4*)(feature + addr);
        float4 o4;
        o4.x = acc[i2][0] + bias + fea.x;
        o4.y = acc[i2][1] + bias + fea.y;
        o4.z = acc[i2][2] + bias + fea.z;
        o4.w = acc[i2][3] + bias + fea.w;
        *(float4*)(out + addr) = o4;
    }
}

// ---------------- launch (R9 structure: knn forked, rest serial) ----------------
extern "C" void kernel_launch(void* const* d_in, const int* in_sizes, int n_in,
                              void* d_out, int out_size) {
    const float* feature = (const float*)d_in[0];
    const float* xyz     = (const float*)d_in[1];
    const float* wq      = (const float*)d_in[2];
    const float* bq      = (const float*)d_in[3];
    const float* wk      = (const float*)d_in[4];
    const float* bk      = (const float*)d_in[5];
    const float* wv      = (const float*)d_in[6];
    const float* bv      = (const float*)d_in[7];
    const float* w1      = (const float*)d_in[8];
    const float* b1      = (const float*)d_in[9];
    float* out = (float*)d_out;

    static cudaStream_t s2 = nullptr;
    static cudaEvent_t  evFork = nullptr, evJoin = nullptr;
    if (s2 == nullptr) {
        cudaStreamCreateWithFlags(&s2, cudaStreamNonBlocking);
        cudaEventCreateWithFlags(&evFork, cudaEventDisableTiming);
        cudaEventCreateWithFlags(&evJoin, cudaEventDisableTiming);
    }

    float* resbuf;
    cudaGetSymbolAddress((void**)&resbuf, d_res);

    // fork: knn runs on s2 concurrently with prep+gemm1 on the main stream
    cudaEventRecord(evFork, 0);
    cudaStreamWaitEvent(s2, evFork, 0);
    knn_kernel<<<dim3(512, 4), 256, 0, s2>>>(xyz);
    cudaEventRecord(evJoin, s2);

    prep_kernel<<<96, 256>>>(wq, bq, wk, bk, wv, bv);
    gemm_kernel<<<dim3(64, 3, 4), 256>>>(xyz, feature);

    // join before attention (needs both PS and knn)
    cudaStreamWaitEvent(0, evJoin, 0);
    attn_kernel<<<BN * NP, 128>>>(resbuf);
    gemm2_kernel<<<dim3(256, 2), 256>>>(w1, b1, feature, out);
}